// round 1
// baseline (speedup 1.0000x reference)
#include <cuda_runtime.h>

#define BB      1024
#define MAXLEN  200
#define FF      64
#define DD      64
#define NEG_PAD (-4294967295.0f)   // -2^32 + 1
#define KSTRIDE 68                  // floats per k row in smem (64 data + 4 pad)

// M[c][d] = sum_e Wq[c][e] * Wk[d][e]  ==  (Wq @ Wk^T)
__device__ float g_M[DD * DD];

__global__ void precompute_M_kernel(const float* __restrict__ Wq,
                                    const float* __restrict__ Wk) {
    int c = blockIdx.x;    // 64 blocks
    int d = threadIdx.x;   // 64 threads
    float s = 0.f;
#pragma unroll
    for (int e = 0; e < DD; ++e)
        s += Wq[c * DD + e] * Wk[d * DD + e];
    g_M[c * DD + d] = s;
}

__global__ __launch_bounds__(256)
void attn_kernel(const float* __restrict__ q,
                 const float* __restrict__ k,
                 const int*   __restrict__ kes_length,
                 const float* __restrict__ fs,
                 const float* __restrict__ bias,
                 const float* __restrict__ Wv,
                 float*       __restrict__ out) {
    extern __shared__ float sm[];
    float* ks   = sm;                       // MAXLEN * KSTRIDE
    float* sa   = ks + MAXLEN * KSTRIDE;    // MAXLEN : score / exp values
    float* sred = sa + MAXLEN;              // 4 * 64 : partial reductions
    float* squ  = sred + 4 * DD;            // 64 : qbar
    float* su   = squ + DD;                 // 64 : u, later w
    float* swr  = su + DD;                  // 32 : warp-reduce scratch

    const int b    = blockIdx.x;
    const int tid  = threadIdx.x;
    const int lane = tid & 31;
    const int warp = tid >> 5;
    const int d    = tid & 63;
    const int g    = tid >> 6;              // 0..3

    // ---- cooperative load of k[b] (200x64 f32) into smem, float4 ----
    const float4* kg  = (const float4*)(k + (size_t)b * MAXLEN * DD);
    float4*       ks4 = (float4*)ks;
    for (int i = tid; i < MAXLEN * (DD / 4); i += 256) {
        int t = i >> 4;          // 16 float4 per row
        int j = i & 15;
        ks4[t * (KSTRIDE / 4) + j] = kg[i];
    }

    // ---- qbar[d] = sum_f fs[f] * q[b,f,d]  (4-way split over f) ----
    const float* qb = q + (size_t)b * FF * DD;
    {
        float acc = 0.f;
#pragma unroll
        for (int f = g; f < FF; f += 4)
            acc += fs[f] * qb[f * DD + d];
        sred[g * DD + d] = acc;
    }
    __syncthreads();
    if (tid < DD)
        squ[tid] = sred[tid] + sred[DD + tid] + sred[2 * DD + tid] + sred[3 * DD + tid];
    __syncthreads();

    // ---- u[d] = sum_c qbar[c] * M[c][d] ----
    if (tid < DD) {
        float s = 0.f;
#pragma unroll
        for (int c = 0; c < DD; ++c)
            s += squ[c] * g_M[c * DD + tid];
        su[tid] = s;
    }
    __syncthreads();   // ks + u both ready

    const int   len   = kes_length[b];
    const float biasD = bias[0] * (float)DD;

    // ---- score: one warp per row, float2 per lane, shuffle reduce ----
    {
        const float2 uv = ((const float2*)su)[lane];
        for (int t = warp; t < MAXLEN; t += 8) {
            float2 kv = ((const float2*)(ks + t * KSTRIDE))[lane];
            float p = kv.x * uv.x + kv.y * uv.y;
#pragma unroll
            for (int o = 16; o; o >>= 1)
                p += __shfl_xor_sync(0xffffffffu, p, o);
            if (lane == 0) {
                float sc  = p + biasD;
                float sig = 1.f / (1.f + expf(-sc));
                float v   = (t < len) ? sig : NEG_PAD;
                sa[t] = v * 0.125f;     // 1/sqrt(64)
            }
        }
    }
    __syncthreads();

    // ---- softmax over 200 (max-subtract handles the all-masked case) ----
    float mval = (tid < MAXLEN) ? sa[tid] : -3.4e38f;
#pragma unroll
    for (int o = 16; o; o >>= 1)
        mval = fmaxf(mval, __shfl_xor_sync(0xffffffffu, mval, o));
    if (lane == 0) swr[warp] = mval;
    __syncthreads();
    if (tid == 0) {
        float mm = swr[0];
#pragma unroll
        for (int i = 1; i < 8; ++i) mm = fmaxf(mm, swr[i]);
        swr[0] = mm;
    }
    __syncthreads();
    const float m = swr[0];

    float e = (tid < MAXLEN) ? expf(sa[tid] - m) : 0.f;
    if (tid < MAXLEN) sa[tid] = e;
    float ssum = e;
#pragma unroll
    for (int o = 16; o; o >>= 1)
        ssum += __shfl_xor_sync(0xffffffffu, ssum, o);
    if (lane == 0) swr[8 + warp] = ssum;
    __syncthreads();
    if (tid == 0) {
        float t0 = 0.f;
#pragma unroll
        for (int i = 0; i < 8; ++i) t0 += swr[8 + i];
        swr[8] = t0;
    }
    __syncthreads();
    const float inv = 1.f / swr[8];

    // ---- w[d] = sum_t e_t * k[t,d]  (4-way split over t) ----
    {
        float wacc = 0.f;
        for (int t = g; t < MAXLEN; t += 4)
            wacc += sa[t] * ks[t * KSTRIDE + d];
        sred[g * DD + d] = wacc;
    }
    __syncthreads();
    if (tid < DD)
        su[tid] = sred[tid] + sred[DD + tid] + sred[2 * DD + tid] + sred[3 * DD + tid];
    __syncthreads();

    // ---- out[b,e] = inv * sum_d w[d] * Wv[d][e] ----
    if (tid < DD) {
        float o = 0.f;
#pragma unroll
        for (int c = 0; c < DD; ++c)
            o += su[c] * Wv[c * DD + tid];
        out[(size_t)b * DD + tid] = o * inv;
    }
}

extern "C" void kernel_launch(void* const* d_in, const int* in_sizes, int n_in,
                              void* d_out, int out_size) {
    const float* q    = (const float*)d_in[0];
    const float* k    = (const float*)d_in[1];
    // d_in[2] = v : UNUSED by the reference computation
    const int*   kes  = (const int*)  d_in[3];
    const float* fs   = (const float*)d_in[4];
    const float* bias = (const float*)d_in[5];
    const float* Wq   = (const float*)d_in[6];
    const float* Wk   = (const float*)d_in[7];
    const float* Wv   = (const float*)d_in[8];
    float*       out  = (float*)d_out;

    const int smem = (MAXLEN * KSTRIDE + MAXLEN + 4 * DD + DD + DD + 32) * (int)sizeof(float);
    cudaFuncSetAttribute(attn_kernel, cudaFuncAttributeMaxDynamicSharedMemorySize, smem);

    precompute_M_kernel<<<DD, DD>>>(Wq, Wk);
    attn_kernel<<<BB, 256, smem>>>(q, k, kes, fs, bias, Wv, out);
}

// round 2
// speedup vs baseline: 1.0063x; 1.0063x over previous
#include <cuda_runtime.h>

#define BB      1024
#define MAXLEN  200
#define FF      64
#define DD      64
#define NEG_PAD (-4294967295.0f)   // -2^32 + 1
#define KSTRIDE 68                  // floats per k row in smem (64 data + 4 pad)

// M[c][d] = sum_e Wq[c][e] * Wk[d][e]  ==  (Wq @ Wk^T)
__device__ float g_M[DD * DD];

__global__ void precompute_M_kernel(const float* __restrict__ Wq,
                                    const float* __restrict__ Wk) {
    int c = blockIdx.x;    // 64 blocks
    int d = threadIdx.x;   // 64 threads
    float s = 0.f;
#pragma unroll
    for (int e = 0; e < DD; ++e)
        s += Wq[c * DD + e] * Wk[d * DD + e];
    g_M[c * DD + d] = s;
}

__global__ __launch_bounds__(256)
void attn_kernel(const float* __restrict__ q,
                 const float* __restrict__ k,
                 const int*   __restrict__ kes_length,
                 const float* __restrict__ fs,
                 const float* __restrict__ bias,
                 const float* __restrict__ Wv,
                 float*       __restrict__ out) {
    extern __shared__ float sm[];
    float* ks   = sm;                       // MAXLEN * KSTRIDE
    float* sa   = ks + MAXLEN * KSTRIDE;    // MAXLEN : score / exp values
    float* sred = sa + MAXLEN;              // 4 * 64 : partial reductions
    float* squ  = sred + 4 * DD;            // 64 : qbar
    float* su   = squ + DD;                 // 64 : u, later w
    float* swr  = su + DD;                  // 32 : warp-reduce scratch

    const int b    = blockIdx.x;
    const int tid  = threadIdx.x;
    const int lane = tid & 31;
    const int warp = tid >> 5;
    const int d    = tid & 63;
    const int g    = tid >> 6;              // 0..3

    // ---- cooperative load of k[b] (200x64 f32) into smem, float4 ----
    const float4* kg  = (const float4*)(k + (size_t)b * MAXLEN * DD);
    float4*       ks4 = (float4*)ks;
    for (int i = tid; i < MAXLEN * (DD / 4); i += 256) {
        int t = i >> 4;          // 16 float4 per row
        int j = i & 15;
        ks4[t * (KSTRIDE / 4) + j] = kg[i];
    }

    // ---- qbar[d] = sum_f fs[f] * q[b,f,d]  (4-way split over f) ----
    const float* qb = q + (size_t)b * FF * DD;
    {
        float acc = 0.f;
#pragma unroll
        for (int f = g; f < FF; f += 4)
            acc += fs[f] * qb[f * DD + d];
        sred[g * DD + d] = acc;
    }
    __syncthreads();
    if (tid < DD)
        squ[tid] = sred[tid] + sred[DD + tid] + sred[2 * DD + tid] + sred[3 * DD + tid];
    __syncthreads();

    // ---- u[d] = sum_c qbar[c] * M[c][d] ----
    if (tid < DD) {
        float s = 0.f;
#pragma unroll
        for (int c = 0; c < DD; ++c)
            s += squ[c] * g_M[c * DD + tid];
        su[tid] = s;
    }
    __syncthreads();   // ks + u both ready

    const int   len   = kes_length[b];
    const float biasD = bias[0] * (float)DD;

    // ---- score: one warp per row, float2 per lane, shuffle reduce ----
    {
        const float2 uv = ((const float2*)su)[lane];
        for (int t = warp; t < MAXLEN; t += 8) {
            float2 kv = ((const float2*)(ks + t * KSTRIDE))[lane];
            float p = kv.x * uv.x + kv.y * uv.y;
#pragma unroll
            for (int o = 16; o; o >>= 1)
                p += __shfl_xor_sync(0xffffffffu, p, o);
            if (lane == 0) {
                float sc  = p + biasD;
                float sig = 1.f / (1.f + expf(-sc));
                float v   = (t < len) ? sig : NEG_PAD;
                sa[t] = v * 0.125f;     // 1/sqrt(64)
            }
        }
    }
    __syncthreads();

    // ---- softmax over 200 (max-subtract handles the all-masked case) ----
    float mval = (tid < MAXLEN) ? sa[tid] : -3.4e38f;
#pragma unroll
    for (int o = 16; o; o >>= 1)
        mval = fmaxf(mval, __shfl_xor_sync(0xffffffffu, mval, o));
    if (lane == 0) swr[warp] = mval;
    __syncthreads();
    if (tid == 0) {
        float mm = swr[0];
#pragma unroll
        for (int i = 1; i < 8; ++i) mm = fmaxf(mm, swr[i]);
        swr[0] = mm;
    }
    __syncthreads();
    const float m = swr[0];

    float e = (tid < MAXLEN) ? expf(sa[tid] - m) : 0.f;
    if (tid < MAXLEN) sa[tid] = e;
    float ssum = e;
#pragma unroll
    for (int o = 16; o; o >>= 1)
        ssum += __shfl_xor_sync(0xffffffffu, ssum, o);
    if (lane == 0) swr[8 + warp] = ssum;
    __syncthreads();
    if (tid == 0) {
        float t0 = 0.f;
#pragma unroll
        for (int i = 0; i < 8; ++i) t0 += swr[8 + i];
        swr[8] = t0;
    }
    __syncthreads();
    const float inv = 1.f / swr[8];

    // ---- w[d] = sum_t e_t * k[t,d]  (4-way split over t) ----
    {
        float wacc = 0.f;
        for (int t = g; t < MAXLEN; t += 4)
            wacc += sa[t] * ks[t * KSTRIDE + d];
        sred[g * DD + d] = wacc;
    }
    __syncthreads();
    if (tid < DD)
        su[tid] = sred[tid] + sred[DD + tid] + sred[2 * DD + tid] + sred[3 * DD + tid];
    __syncthreads();

    // ---- out[b,e] = inv * sum_d w[d] * Wv[d][e] ----
    if (tid < DD) {
        float o = 0.f;
#pragma unroll
        for (int c = 0; c < DD; ++c)
            o += su[c] * Wv[c * DD + tid];
        out[(size_t)b * DD + tid] = o * inv;
    }
}

extern "C" void kernel_launch(void* const* d_in, const int* in_sizes, int n_in,
                              void* d_out, int out_size) {
    const float* q    = (const float*)d_in[0];
    const float* k    = (const float*)d_in[1];
    // d_in[2] = v : UNUSED by the reference computation
    const int*   kes  = (const int*)  d_in[3];
    const float* fs   = (const float*)d_in[4];
    const float* bias = (const float*)d_in[5];
    const float* Wq   = (const float*)d_in[6];
    const float* Wk   = (const float*)d_in[7];
    const float* Wv   = (const float*)d_in[8];
    float*       out  = (float*)d_out;

    const int smem = (MAXLEN * KSTRIDE + MAXLEN + 4 * DD + DD + DD + 32) * (int)sizeof(float);
    cudaFuncSetAttribute(attn_kernel, cudaFuncAttributeMaxDynamicSharedMemorySize, smem);

    precompute_M_kernel<<<DD, DD>>>(Wq, Wk);
    attn_kernel<<<BB, 256, smem>>>(q, k, kes, fs, bias, Wv, out);
}

// round 3
// speedup vs baseline: 1.3090x; 1.3007x over previous
#include <cuda_runtime.h>

#define BB      1024
#define MAXLEN  200
#define FF      64
#define DD      64
#define NEG_PAD (-4294967295.0f)   // -2^32 + 1
#define NW      16                  // warps per CTA
#define NT      512
#define RPW     13                  // ceil(200/16) rows per warp (max)

__global__ __launch_bounds__(NT, 2)
void attn_kernel(const float* __restrict__ q,
                 const float* __restrict__ k,
                 const int*   __restrict__ kes_length,
                 const float* __restrict__ fs,
                 const float* __restrict__ bias,
                 const float* __restrict__ Wq,
                 const float* __restrict__ Wk,
                 const float* __restrict__ Wv,
                 float*       __restrict__ out) {
    __shared__ float sa[MAXLEN];        // scores / exp values
    __shared__ float sred[8 * DD];      // 8-group partial reductions
    __shared__ float spart[NW * DD];    // per-warp weighted-sum partials
    __shared__ float squ[DD];           // qbar
    __shared__ float stmp[DD];          // qbar @ Wq
    __shared__ float su[DD];            // u, then w
    __shared__ float swr[NW];           // warp-reduce scratch

    const int b    = blockIdx.x;
    const int tid  = threadIdx.x;
    const int lane = tid & 31;
    const int warp = tid >> 5;
    const int d    = tid & 63;
    const int g    = tid >> 6;          // 0..7

    // ---- issue k loads FIRST (independent of everything below) ----
    // warp w owns rows t = w, w+16, w+32, ... ; lane holds float2 (cols 2*lane..)
    const float2* kb2 = (const float2*)(k + (size_t)b * MAXLEN * DD);
    float2 kreg[RPW];
#pragma unroll
    for (int i = 0; i < RPW; ++i) {
        int t = warp + i * NW;
        if (t < MAXLEN)
            kreg[i] = kb2[t * (DD / 2) + lane];
    }

    // ---- qbar[d] = sum_f fs[f] * q[b,f,d]  (8-way split over f) ----
    const float* qb = q + (size_t)b * FF * DD;
    {
        float acc = 0.f;
#pragma unroll
        for (int fi = 0; fi < FF / 8; ++fi) {
            int f = g + fi * 8;
            acc += fs[f] * qb[f * DD + d];
        }
        sred[g * DD + d] = acc;
    }
    __syncthreads();
    if (tid < DD) {
        float s = 0.f;
#pragma unroll
        for (int i = 0; i < 8; ++i) s += sred[i * DD + tid];
        squ[tid] = s;
    }
    __syncthreads();

    // ---- tmp[e] = sum_c qbar[c] * Wq[c,e]  (row-combination, coalesced) ----
    {
        float acc = 0.f;
#pragma unroll
        for (int ci = 0; ci < 8; ++ci) {
            int c = g * 8 + ci;
            acc += squ[c] * Wq[c * DD + d];
        }
        sred[g * DD + d] = acc;
    }
    __syncthreads();
    if (tid < DD) {
        float s = 0.f;
#pragma unroll
        for (int i = 0; i < 8; ++i) s += sred[i * DD + tid];
        stmp[tid] = s;
    }
    __syncthreads();

    // ---- u[r] = sum_e tmp[e] * Wk[r,e]  (warp per row, coalesced row read) ----
    {
        const float2 tv = ((const float2*)stmp)[lane];
#pragma unroll
        for (int r = 0; r < 4; ++r) {
            int row = warp * 4 + r;
            float2 wv = ((const float2*)(Wk + row * DD))[lane];
            float p = wv.x * tv.x + wv.y * tv.y;
#pragma unroll
            for (int o = 16; o; o >>= 1)
                p += __shfl_xor_sync(0xffffffffu, p, o);
            if (lane == 0) su[row] = p;
        }
    }
    __syncthreads();

    // ---- scores from register-resident k ----
    const int   len   = kes_length[b];
    const float biasD = bias[0] * (float)DD;
    {
        const float2 uv = ((const float2*)su)[lane];
#pragma unroll
        for (int i = 0; i < RPW; ++i) {
            int t = warp + i * NW;
            if (t < MAXLEN) {
                float p = kreg[i].x * uv.x + kreg[i].y * uv.y;
#pragma unroll
                for (int o = 16; o; o >>= 1)
                    p += __shfl_xor_sync(0xffffffffu, p, o);
                if (lane == 0) {
                    float sig = 1.f / (1.f + expf(-(p + biasD)));
                    sa[t] = ((t < len) ? sig : NEG_PAD) * 0.125f;
                }
            }
        }
    }
    __syncthreads();

    // ---- softmax over 200 ----
    float mval = (tid < MAXLEN) ? sa[tid] : -3.4e38f;
#pragma unroll
    for (int o = 16; o; o >>= 1)
        mval = fmaxf(mval, __shfl_xor_sync(0xffffffffu, mval, o));
    if (lane == 0) swr[warp] = mval;
    __syncthreads();
    if (tid == 0) {
        float mm = swr[0];
#pragma unroll
        for (int i = 1; i < NW; ++i) mm = fmaxf(mm, swr[i]);
        swr[0] = mm;
    }
    __syncthreads();
    const float m = swr[0];
    __syncthreads();   // protect swr[0] before reuse for sum

    float e = (tid < MAXLEN) ? expf(sa[tid] - m) : 0.f;
    if (tid < MAXLEN) sa[tid] = e;
    float ssum = e;
#pragma unroll
    for (int o = 16; o; o >>= 1)
        ssum += __shfl_xor_sync(0xffffffffu, ssum, o);
    if (lane == 0) swr[warp] = ssum;
    __syncthreads();
    if (tid == 0) {
        float t0 = 0.f;
#pragma unroll
        for (int i = 0; i < NW; ++i) t0 += swr[i];
        swr[0] = t0;
    }
    __syncthreads();
    const float inv = 1.f / swr[0];

    // ---- w[d] = sum_t e_t * k[t,d]  from registers, per-warp partials ----
    {
        float2 wa = make_float2(0.f, 0.f);
#pragma unroll
        for (int i = 0; i < RPW; ++i) {
            int t = warp + i * NW;
            if (t < MAXLEN) {
                float et = sa[t];
                wa.x += et * kreg[i].x;
                wa.y += et * kreg[i].y;
            }
        }
        ((float2*)(spart + warp * DD))[lane] = wa;
    }
    __syncthreads();
    if (tid < DD) {
        float s = 0.f;
#pragma unroll
        for (int i = 0; i < NW; ++i) s += spart[i * DD + tid];
        su[tid] = s;
    }
    __syncthreads();

    // ---- out[b,e] = inv * sum_c w[c] * Wv[c,e]  (row-combination, coalesced) ----
    {
        float acc = 0.f;
#pragma unroll
        for (int ci = 0; ci < 8; ++ci) {
            int c = g * 8 + ci;
            acc += su[c] * Wv[c * DD + d];
        }
        sred[g * DD + d] = acc;
    }
    __syncthreads();
    if (tid < DD) {
        float s = 0.f;
#pragma unroll
        for (int i = 0; i < 8; ++i) s += sred[i * DD + tid];
        out[(size_t)b * DD + tid] = s * inv;
    }
}

extern "C" void kernel_launch(void* const* d_in, const int* in_sizes, int n_in,
                              void* d_out, int out_size) {
    const float* q    = (const float*)d_in[0];
    const float* k    = (const float*)d_in[1];
    // d_in[2] = v : unused by the reference computation
    const int*   kes  = (const int*)  d_in[3];
    const float* fs   = (const float*)d_in[4];
    const float* bias = (const float*)d_in[5];
    const float* Wq   = (const float*)d_in[6];
    const float* Wk   = (const float*)d_in[7];
    const float* Wv   = (const float*)d_in[8];
    float*       out  = (float*)d_out;

    attn_kernel<<<BB, NT>>>(q, k, kes, fs, bias, Wq, Wk, Wv, out);
}

// round 4
// speedup vs baseline: 1.5438x; 1.1794x over previous
#include <cuda_runtime.h>

#define BB      1024
#define MAXLEN  200
#define FF      64
#define DD      64
#define NEG_PAD (-4294967295.0f)   // -2^32 + 1
#define NW      8                   // warps per CTA
#define NT      256
#define RPW     25                  // rows per warp (200/8)
#define BATCH   5

__global__ __launch_bounds__(NT, 5)
void attn_kernel(const float* __restrict__ q,
                 const float* __restrict__ k,
                 const int*   __restrict__ kes_length,
                 const float* __restrict__ fs,
                 const float* __restrict__ bias,
                 const float* __restrict__ Wq,
                 const float* __restrict__ Wk,
                 const float* __restrict__ Wv,
                 float*       __restrict__ out) {
    __shared__ float sred[4 * DD];      // 4-group partial reductions
    __shared__ float spart[NW * DD];    // per-warp weighted-sum partials
    __shared__ float squ[DD];           // qbar
    __shared__ float stmp[DD];          // qbar @ Wq
    __shared__ float su[DD];            // u, then w
    __shared__ float swr[NW];           // per-warp exp-sum

    const int b    = blockIdx.x;
    const int tid  = threadIdx.x;
    const int lane = tid & 31;
    const int warp = tid >> 5;
    const int d    = tid & 63;
    const int g    = tid >> 6;          // 0..3

    const float2* kb2 = (const float2*)(k + (size_t)b * MAXLEN * DD);
    const int t0 = warp * RPW;

    // ---- prefetch first k batch (independent of everything below) ----
    float2 kv[BATCH];
#pragma unroll
    for (int j = 0; j < BATCH; ++j)
        kv[j] = kb2[(t0 + j) * (DD / 2) + lane];

    // ---- qbar[d] = sum_f fs[f] * q[b,f,d]  (4-way split over f) ----
    const float* qb = q + (size_t)b * FF * DD;
    {
        float acc = 0.f;
#pragma unroll
        for (int fi = 0; fi < FF / 4; ++fi) {
            int f = g + fi * 4;
            acc += fs[f] * qb[f * DD + d];
        }
        sred[g * DD + d] = acc;
    }
    __syncthreads();
    if (tid < DD)
        squ[tid] = sred[tid] + sred[DD + tid] + sred[2 * DD + tid] + sred[3 * DD + tid];
    __syncthreads();

    // ---- tmp[e] = sum_c qbar[c] * Wq[c,e]  (row-combination, coalesced) ----
    {
        float acc = 0.f;
#pragma unroll
        for (int ci = 0; ci < 16; ++ci) {
            int c = g * 16 + ci;
            acc += squ[c] * Wq[c * DD + d];
        }
        sred[g * DD + d] = acc;
    }
    __syncthreads();
    if (tid < DD)
        stmp[tid] = sred[tid] + sred[DD + tid] + sred[2 * DD + tid] + sred[3 * DD + tid];
    __syncthreads();

    // ---- u[r] = sum_e tmp[e] * Wk[r,e]  (warp per row, coalesced) ----
    {
        const float2 tv = ((const float2*)stmp)[lane];
#pragma unroll
        for (int r = 0; r < DD / NW; ++r) {
            int row = warp * (DD / NW) + r;
            float2 wv = ((const float2*)(Wk + row * DD))[lane];
            float p = wv.x * tv.x + wv.y * tv.y;
#pragma unroll
            for (int o = 16; o; o >>= 1)
                p += __shfl_xor_sync(0xffffffffu, p, o);
            if (lane == 0) su[row] = p;
        }
    }
    __syncthreads();

    // ---- single streaming pass: score -> exp -> weighted accumulate ----
    const int   len   = kes_length[b];
    const float biasD = bias[0] * (float)DD;
    const float mfill = (len == 0) ? 1.f : 0.f;   // len==0: uniform softmax
    const float2 uv   = ((const float2*)su)[lane];

    float2 wa   = make_float2(0.f, 0.f);
    float  esum = 0.f;

#pragma unroll
    for (int base = 0; base < RPW; base += BATCH) {
        float2 kn[BATCH];
        const bool more = (base + BATCH < RPW);
        if (more) {
#pragma unroll
            for (int j = 0; j < BATCH; ++j)
                kn[j] = kb2[(t0 + base + BATCH + j) * (DD / 2) + lane];
        }
#pragma unroll
        for (int j = 0; j < BATCH; ++j) {
            float p = kv[j].x * uv.x + kv[j].y * uv.y;
#pragma unroll
            for (int o = 16; o; o >>= 1)
                p += __shfl_xor_sync(0xffffffffu, p, o);   // all lanes get score
            int   t   = t0 + base + j;
            float sig = 1.f / (1.f + expf(-(p + biasD)));
            float e   = (t < len) ? expf(sig * 0.125f) : mfill;
            wa.x += e * kv[j].x;
            wa.y += e * kv[j].y;
            esum += e;
        }
        if (more) {
#pragma unroll
            for (int j = 0; j < BATCH; ++j)
                kv[j] = kn[j];
        }
    }

    ((float2*)(spart + warp * DD))[lane] = wa;
    if (lane == 0) swr[warp] = esum;
    __syncthreads();

    // ---- w[d] = cross-warp reduce ----
    if (tid < DD) {
        float s = 0.f;
#pragma unroll
        for (int i = 0; i < NW; ++i) s += spart[i * DD + tid];
        su[tid] = s;
    }
    __syncthreads();

    float tot = 0.f;
#pragma unroll
    for (int i = 0; i < NW; ++i) tot += swr[i];
    const float inv = 1.f / tot;

    // ---- out[b,e] = inv * sum_c w[c] * Wv[c,e] ----
    {
        float acc = 0.f;
#pragma unroll
        for (int ci = 0; ci < 16; ++ci) {
            int c = g * 16 + ci;
            acc += su[c] * Wv[c * DD + d];
        }
        sred[g * DD + d] = acc;
    }
    __syncthreads();
    if (tid < DD) {
        float s = sred[tid] + sred[DD + tid] + sred[2 * DD + tid] + sred[3 * DD + tid];
        out[(size_t)b * DD + tid] = s * inv;
    }
}

extern "C" void kernel_launch(void* const* d_in, const int* in_sizes, int n_in,
                              void* d_out, int out_size) {
    const float* q    = (const float*)d_in[0];
    const float* k    = (const float*)d_in[1];
    // d_in[2] = v : unused by the reference computation
    const int*   kes  = (const int*)  d_in[3];
    const float* fs   = (const float*)d_in[4];
    const float* bias = (const float*)d_in[5];
    const float* Wq   = (const float*)d_in[6];
    const float* Wk   = (const float*)d_in[7];
    const float* Wv   = (const float*)d_in[8];
    float*       out  = (float*)d_out;

    attn_kernel<<<BB, NT>>>(q, k, kes, fs, bias, Wq, Wk, Wv, out);
}

// round 5
// speedup vs baseline: 1.8750x; 1.2145x over previous
#include <cuda_runtime.h>
#include <cstdint>

#define BB      1024
#define MAXLEN  200
#define FF      64
#define DD      64
#define NW      8
#define NT      256
#define CH      50          // k rows per chunk
#define NCHUNK  4           // 4 * 50 = 200
#define CPU16   ((CH * DD * 4) / 16)   // 800 16-byte units per chunk

__device__ __forceinline__ void cp_async16(uint32_t saddr, const void* gaddr) {
    asm volatile("cp.async.cg.shared.global [%0], [%1], 16;" :: "r"(saddr), "l"(gaddr) : "memory");
}
__device__ __forceinline__ void cp_commit() {
    asm volatile("cp.async.commit_group;" ::: "memory");
}
template<int N> __device__ __forceinline__ void cp_wait() {
    asm volatile("cp.async.wait_group %0;" :: "n"(N) : "memory");
}

__global__ __launch_bounds__(NT, 5)
void attn_kernel(const float* __restrict__ q,
                 const float* __restrict__ k,
                 const int*   __restrict__ kes_length,
                 const float* __restrict__ fs,
                 const float* __restrict__ bias,
                 const float* __restrict__ Wq,
                 const float* __restrict__ Wk,
                 const float* __restrict__ Wv,
                 float*       __restrict__ out) {
    __shared__ float kbuf[2][CH * DD];   // 2 x 12.8 KB double-buffered k tile
    __shared__ float spart[16 * DD];     // 16-group partials (q-reduce, matvecs, w)
    __shared__ float sred[16];           // (unused small scratch kept minimal)
    __shared__ float squ[DD];            // qbar
    __shared__ float stmp[DD];           // qbar @ Wq
    __shared__ float su[DD];             // u, then w
    __shared__ float swr[16];            // per-half-warp exp-sums

    const int b    = blockIdx.x;
    const int tid  = threadIdx.x;
    const int hw   = tid >> 4;           // half-warp id 0..15
    const int l16  = tid & 15;           // lane within half-warp

    const float* kb = k + (size_t)b * MAXLEN * DD;

    // ---- kick off async k staging for chunks 0 and 1 immediately ----
    uint32_t sb0 = (uint32_t)__cvta_generic_to_shared(kbuf[0]);
    uint32_t sb1 = (uint32_t)__cvta_generic_to_shared(kbuf[1]);
    {
        const char* g0 = (const char*)kb;
        cp_async16(sb0 + tid * 16,         g0 + tid * 16);
        cp_async16(sb0 + (tid + 256) * 16, g0 + (tid + 256) * 16);
        cp_async16(sb0 + (tid + 512) * 16, g0 + (tid + 512) * 16);
        if (tid < CPU16 - 768)
            cp_async16(sb0 + (tid + 768) * 16, g0 + (tid + 768) * 16);
        cp_commit();
        const char* g1 = (const char*)(kb + CH * DD);
        cp_async16(sb1 + tid * 16,         g1 + tid * 16);
        cp_async16(sb1 + (tid + 256) * 16, g1 + (tid + 256) * 16);
        cp_async16(sb1 + (tid + 512) * 16, g1 + (tid + 512) * 16);
        if (tid < CPU16 - 768)
            cp_async16(sb1 + (tid + 768) * 16, g1 + (tid + 768) * 16);
        cp_commit();
    }

    // ---- qbar[d] = sum_f fs[f] * q[b,f,d]   (float4, 16-way f split) ----
    {
        const float4* qb4 = (const float4*)(q + (size_t)b * FF * DD);
        float4 a = make_float4(0.f, 0.f, 0.f, 0.f);
#pragma unroll
        for (int fi = 0; fi < 4; ++fi) {
            int f = hw + 16 * fi;
            float s = fs[f];
            float4 v = qb4[f * 16 + l16];
            a.x += s * v.x; a.y += s * v.y; a.z += s * v.z; a.w += s * v.w;
        }
        ((float4*)spart)[hw * 16 + l16] = a;
    }
    __syncthreads();
    if (tid < DD) {
        float s = 0.f;
#pragma unroll
        for (int i = 0; i < 16; ++i) s += spart[i * DD + tid];
        squ[tid] = s;
    }
    __syncthreads();

    // ---- tmp[e] = sum_c qbar[c] * Wq[c,e]   (float4 row-combination) ----
    {
        float4 a = make_float4(0.f, 0.f, 0.f, 0.f);
#pragma unroll
        for (int ci = 0; ci < 4; ++ci) {
            int c = hw * 4 + ci;
            float s = squ[c];
            float4 v = ((const float4*)Wq)[c * 16 + l16];
            a.x += s * v.x; a.y += s * v.y; a.z += s * v.z; a.w += s * v.w;
        }
        ((float4*)spart)[hw * 16 + l16] = a;
    }
    __syncthreads();
    if (tid < DD) {
        float s = 0.f;
#pragma unroll
        for (int i = 0; i < 16; ++i) s += spart[i * DD + tid];
        stmp[tid] = s;
    }
    __syncthreads();

    // ---- u[row] = sum_e tmp[e] * Wk[row,e]  (half-warp per row, float4) ----
    {
        float4 tv = ((const float4*)stmp)[l16];
#pragma unroll
        for (int r = 0; r < 4; ++r) {
            int row = hw + 16 * r;
            float4 wv = ((const float4*)(Wk + row * DD))[l16];
            float p = wv.x * tv.x + wv.y * tv.y + wv.z * tv.z + wv.w * tv.w;
#pragma unroll
            for (int o = 8; o; o >>= 1)
                p += __shfl_xor_sync(0xffffffffu, p, o);
            if (l16 == 0) su[row] = p;
        }
    }
    __syncthreads();

    // ---- main streaming pass over k chunks ----
    const int   len   = kes_length[b];
    const float biasD = bias[0] * (float)DD;
    const float mfill = (len == 0) ? 1.f : 0.f;
    const float4 uv   = ((const float4*)su)[l16];

    float4 wa   = make_float4(0.f, 0.f, 0.f, 0.f);
    float  esum = 0.f;

#pragma unroll
    for (int c = 0; c < NCHUNK; ++c) {
        if (c < NCHUNK - 1) cp_wait<1>(); else cp_wait<0>();
        __syncthreads();

        const float4* kt = (const float4*)kbuf[c & 1];
#pragma unroll
        for (int i = 0; i < 4; ++i) {
            int rl = hw + 16 * i;
            if (rl < CH) {
                float4 kv = kt[rl * 16 + l16];
                float p = kv.x * uv.x + kv.y * uv.y + kv.z * uv.z + kv.w * uv.w;
#pragma unroll
                for (int o = 8; o; o >>= 1)
                    p += __shfl_xor_sync(0xffffffffu, p, o);
                int   t   = c * CH + rl;
                float sig = 1.f / (1.f + expf(-(p + biasD)));
                float e   = (t < len) ? expf(sig * 0.125f) : mfill;
                wa.x += e * kv.x; wa.y += e * kv.y;
                wa.z += e * kv.z; wa.w += e * kv.w;
                esum += e;
            }
        }

        if (c < NCHUNK - 2) {
            __syncthreads();    // everyone done reading kbuf[c&1] before overwrite
            const char* gc = (const char*)(kb + (c + 2) * CH * DD);
            uint32_t sbc = (c & 1) ? sb1 : sb0;
            cp_async16(sbc + tid * 16,         gc + tid * 16);
            cp_async16(sbc + (tid + 256) * 16, gc + (tid + 256) * 16);
            cp_async16(sbc + (tid + 512) * 16, gc + (tid + 512) * 16);
            if (tid < CPU16 - 768)
                cp_async16(sbc + (tid + 768) * 16, gc + (tid + 768) * 16);
            cp_commit();
        }
    }

    __syncthreads();   // spart free for reuse
    ((float4*)spart)[hw * 16 + l16] = wa;
    if (l16 == 0) swr[hw] = esum;
    __syncthreads();

    // ---- w[d] = cross-half-warp reduce ----
    if (tid < DD) {
        float s = 0.f;
#pragma unroll
        for (int i = 0; i < 16; ++i) s += spart[i * DD + tid];
        su[tid] = s;
    }
    __syncthreads();

    // ---- out[b,e] = inv * sum_c w[c] * Wv[c,e]   (float4 row-combination) ----
    {
        float4 a = make_float4(0.f, 0.f, 0.f, 0.f);
#pragma unroll
        for (int ci = 0; ci < 4; ++ci) {
            int c = hw * 4 + ci;
            float s = su[c];
            float4 v = ((const float4*)Wv)[c * 16 + l16];
            a.x += s * v.x; a.y += s * v.y; a.z += s * v.z; a.w += s * v.w;
        }
        ((float4*)spart)[hw * 16 + l16] = a;
    }
    __syncthreads();
    if (tid < DD) {
        float tot = 0.f;
#pragma unroll
        for (int i = 0; i < 16; ++i) tot += swr[i];
        float s = 0.f;
#pragma unroll
        for (int i = 0; i < 16; ++i) s += spart[i * DD + tid];
        out[(size_t)b * DD + tid] = s * (1.f / tot);
    }
    (void)sred;
}

extern "C" void kernel_launch(void* const* d_in, const int* in_sizes, int n_in,
                              void* d_out, int out_size) {
    const float* q    = (const float*)d_in[0];
    const float* k    = (const float*)d_in[1];
    // d_in[2] = v : unused by the reference computation
    const int*   kes  = (const int*)  d_in[3];
    const float* fs   = (const float*)d_in[4];
    const float* bias = (const float*)d_in[5];
    const float* Wq   = (const float*)d_in[6];
    const float* Wk   = (const float*)d_in[7];
    const float* Wv   = (const float*)d_in[8];
    float*       out  = (float*)d_out;

    attn_kernel<<<BB, NT>>>(q, k, kes, fs, bias, Wq, Wk, Wv, out);
}

// round 6
// speedup vs baseline: 2.0709x; 1.1045x over previous
#include <cuda_runtime.h>
#include <cstdint>

#define BB      1024
#define MAXLEN  200
#define FF      64
#define DD      64
#define NT      256
#define CH      50          // k rows per chunk
#define NCHUNK  4           // 4 * 50 = 200
#define CPU16   ((CH * DD * 4) / 16)   // 800 16-byte units per chunk

__device__ __forceinline__ void cp_async16(uint32_t saddr, const void* gaddr) {
    asm volatile("cp.async.cg.shared.global [%0], [%1], 16;" :: "r"(saddr), "l"(gaddr) : "memory");
}
__device__ __forceinline__ void cp_commit() {
    asm volatile("cp.async.commit_group;" ::: "memory");
}
template<int N> __device__ __forceinline__ void cp_wait() {
    asm volatile("cp.async.wait_group %0;" :: "n"(N) : "memory");
}
// sigmoid(x) = 0.5 * tanh(0.5x) + 0.5  (1 MUFU)
__device__ __forceinline__ float fast_sigmoid(float x) {
    float t;
    asm("tanh.approx.f32 %0, %1;" : "=f"(t) : "f"(0.5f * x));
    return fmaf(0.5f, t, 0.5f);
}
// exp(x/8) = 2^(x * 0.125*log2(e))  (1 MUFU)
__device__ __forceinline__ float fast_exp8(float x) {
    float e;
    asm("ex2.approx.f32 %0, %1;" : "=f"(e) : "f"(x * 0.18033688011112042f));
    return e;
}

__global__ __launch_bounds__(NT, 7)
void attn_kernel(const float* __restrict__ q,
                 const float* __restrict__ k,
                 const int*   __restrict__ kes_length,
                 const float* __restrict__ fs,
                 const float* __restrict__ bias,
                 const float* __restrict__ Wq,
                 const float* __restrict__ Wk,
                 const float* __restrict__ Wv,
                 float*       __restrict__ out) {
    __shared__ float kbuf[2][CH * DD];   // 2 x 12.8 KB double-buffered k tile
    __shared__ float spart[16 * DD];     // 16-group partials
    __shared__ float squ[DD];            // qbar
    __shared__ float stmp[DD];           // qbar @ Wq
    __shared__ float su[DD];             // u, then w
    __shared__ float swr[16];            // per-half-warp exp-sums

    const int b    = blockIdx.x;
    const int tid  = threadIdx.x;
    const int hw   = tid >> 4;           // half-warp id 0..15
    const int l16  = tid & 15;

    const float* kb = k + (size_t)b * MAXLEN * DD;

    // ---- kick off async k staging for chunks 0 and 1 immediately ----
    uint32_t sb0 = (uint32_t)__cvta_generic_to_shared(kbuf[0]);
    uint32_t sb1 = (uint32_t)__cvta_generic_to_shared(kbuf[1]);
    {
        const char* g0 = (const char*)kb;
        cp_async16(sb0 + tid * 16,         g0 + tid * 16);
        cp_async16(sb0 + (tid + 256) * 16, g0 + (tid + 256) * 16);
        cp_async16(sb0 + (tid + 512) * 16, g0 + (tid + 512) * 16);
        if (tid < CPU16 - 768)
            cp_async16(sb0 + (tid + 768) * 16, g0 + (tid + 768) * 16);
        cp_commit();
        const char* g1 = (const char*)(kb + CH * DD);
        cp_async16(sb1 + tid * 16,         g1 + tid * 16);
        cp_async16(sb1 + (tid + 256) * 16, g1 + (tid + 256) * 16);
        cp_async16(sb1 + (tid + 512) * 16, g1 + (tid + 512) * 16);
        if (tid < CPU16 - 768)
            cp_async16(sb1 + (tid + 768) * 16, g1 + (tid + 768) * 16);
        cp_commit();
    }

    // ---- qbar[d] = sum_f fs[f] * q[b,f,d]   (float4, 16-way f split) ----
    {
        const float4* qb4 = (const float4*)(q + (size_t)b * FF * DD);
        float4 a = make_float4(0.f, 0.f, 0.f, 0.f);
#pragma unroll
        for (int fi = 0; fi < 4; ++fi) {
            int f = hw + 16 * fi;
            float s = fs[f];
            float4 v = qb4[f * 16 + l16];
            a.x += s * v.x; a.y += s * v.y; a.z += s * v.z; a.w += s * v.w;
        }
        ((float4*)spart)[hw * 16 + l16] = a;
    }
    __syncthreads();
    if (tid < DD) {
        float s = 0.f;
#pragma unroll
        for (int i = 0; i < 16; ++i) s += spart[i * DD + tid];
        squ[tid] = s;
    }
    __syncthreads();

    // ---- tmp[e] = sum_c qbar[c] * Wq[c,e]   (float4 row-combination) ----
    {
        float4 a = make_float4(0.f, 0.f, 0.f, 0.f);
#pragma unroll
        for (int ci = 0; ci < 4; ++ci) {
            int c = hw * 4 + ci;
            float s = squ[c];
            float4 v = ((const float4*)Wq)[c * 16 + l16];
            a.x += s * v.x; a.y += s * v.y; a.z += s * v.z; a.w += s * v.w;
        }
        ((float4*)spart)[hw * 16 + l16] = a;
    }
    __syncthreads();
    if (tid < DD) {
        float s = 0.f;
#pragma unroll
        for (int i = 0; i < 16; ++i) s += spart[i * DD + tid];
        stmp[tid] = s;
    }
    __syncthreads();

    // ---- u[row] = sum_e tmp[e] * Wk[row,e]  (half-warp per row, float4) ----
    {
        float4 tv = ((const float4*)stmp)[l16];
#pragma unroll
        for (int r = 0; r < 4; ++r) {
            int row = hw + 16 * r;
            float4 wv = ((const float4*)(Wk + row * DD))[l16];
            float p = wv.x * tv.x + wv.y * tv.y + wv.z * tv.z + wv.w * tv.w;
#pragma unroll
            for (int o = 8; o; o >>= 1)
                p += __shfl_xor_sync(0xffffffffu, p, o);
            if (l16 == 0) su[row] = p;
        }
    }
    __syncthreads();

    // ---- main streaming pass over k chunks ----
    const int   len   = kes_length[b];
    const float biasD = bias[0] * (float)DD;
    const float mfill = (len == 0) ? 1.f : 0.f;
    const float4 uv   = ((const float4*)su)[l16];

    float4 wa   = make_float4(0.f, 0.f, 0.f, 0.f);
    float  esum = 0.f;

#pragma unroll
    for (int c = 0; c < NCHUNK; ++c) {
        if (c < NCHUNK - 1) cp_wait<1>(); else cp_wait<0>();
        __syncthreads();

        const float4* kt = (const float4*)kbuf[c & 1];
#pragma unroll
        for (int i = 0; i < 4; ++i) {
            int rl = hw + 16 * i;
            if (rl < CH) {
                float4 kv = kt[rl * 16 + l16];
                float p = kv.x * uv.x + kv.y * uv.y + kv.z * uv.z + kv.w * uv.w;
#pragma unroll
                for (int o = 8; o; o >>= 1)
                    p += __shfl_xor_sync(0xffffffffu, p, o);
                int   t   = c * CH + rl;
                float e   = (t < len) ? fast_exp8(fast_sigmoid(p + biasD)) : mfill;
                wa.x += e * kv.x; wa.y += e * kv.y;
                wa.z += e * kv.z; wa.w += e * kv.w;
                esum += e;
            }
        }

        if (c < NCHUNK - 2) {
            __syncthreads();    // everyone done reading kbuf[c&1] before overwrite
            const char* gc = (const char*)(kb + (c + 2) * CH * DD);
            uint32_t sbc = (c & 1) ? sb1 : sb0;
            cp_async16(sbc + tid * 16,         gc + tid * 16);
            cp_async16(sbc + (tid + 256) * 16, gc + (tid + 256) * 16);
            cp_async16(sbc + (tid + 512) * 16, gc + (tid + 512) * 16);
            if (tid < CPU16 - 768)
                cp_async16(sbc + (tid + 768) * 16, gc + (tid + 768) * 16);
            cp_commit();
        }
    }

    __syncthreads();   // spart free for reuse
    ((float4*)spart)[hw * 16 + l16] = wa;
    if (l16 == 0) swr[hw] = esum;
    __syncthreads();

    // ---- w[d] = cross-half-warp reduce ----
    if (tid < DD) {
        float s = 0.f;
#pragma unroll
        for (int i = 0; i < 16; ++i) s += spart[i * DD + tid];
        su[tid] = s;
    }
    __syncthreads();

    // ---- out[b,e] = inv * sum_c w[c] * Wv[c,e]   (float4 row-combination) ----
    {
        float4 a = make_float4(0.f, 0.f, 0.f, 0.f);
#pragma unroll
        for (int ci = 0; ci < 4; ++ci) {
            int c = hw * 4 + ci;
            float s = su[c];
            float4 v = ((const float4*)Wv)[c * 16 + l16];
            a.x += s * v.x; a.y += s * v.y; a.z += s * v.z; a.w += s * v.w;
        }
        ((float4*)spart)[hw * 16 + l16] = a;
    }
    __syncthreads();
    if (tid < DD) {
        float tot = 0.f;
#pragma unroll
        for (int i = 0; i < 16; ++i) tot += swr[i];
        float s = 0.f;
#pragma unroll
        for (int i = 0; i < 16; ++i) s += spart[i * DD + tid];
        out[(size_t)b * DD + tid] = s * (1.f / tot);
    }
}

extern "C" void kernel_launch(void* const* d_in, const int* in_sizes, int n_in,
                              void* d_out, int out_size) {
    const float* q    = (const float*)d_in[0];
    const float* k    = (const float*)d_in[1];
    // d_in[2] = v : unused by the reference computation
    const int*   kes  = (const int*)  d_in[3];
    const float* fs   = (const float*)d_in[4];
    const float* bias = (const float*)d_in[5];
    const float* Wq   = (const float*)d_in[6];
    const float* Wk   = (const float*)d_in[7];
    const float* Wv   = (const float*)d_in[8];
    float*       out  = (float*)d_out;

    cudaFuncSetAttribute(attn_kernel, cudaFuncAttributePreferredSharedMemoryCarveout, 100);
    attn_kernel<<<BB, NT>>>(q, k, kes, fs, bias, Wq, Wk, Wv, out);
}

// round 7
// speedup vs baseline: 2.0748x; 1.0019x over previous
#include <cuda_runtime.h>
#include <cstdint>

#define BB      1024
#define MAXLEN  200
#define FF      64
#define DD      64
#define NT      256
#define RPW     25                  // rows per warp
#define BT      5                   // rows per batch
#define NBATCH  5                   // batches per warp
#define BUNITS  ((BT * DD * 4) / 16)   // 80 16-byte units per batch
#define BFLOATS (BT * DD)           // 320 floats per batch buffer

__device__ __forceinline__ void cp_async16(uint32_t saddr, const void* gaddr) {
    asm volatile("cp.async.cg.shared.global [%0], [%1], 16;" :: "r"(saddr), "l"(gaddr) : "memory");
}
__device__ __forceinline__ void cp_commit() {
    asm volatile("cp.async.commit_group;" ::: "memory");
}
template<int N> __device__ __forceinline__ void cp_wait() {
    asm volatile("cp.async.wait_group %0;" :: "n"(N) : "memory");
}
__device__ __forceinline__ float fast_sigmoid(float x) {
    float t;
    asm("tanh.approx.f32 %0, %1;" : "=f"(t) : "f"(0.5f * x));
    return fmaf(0.5f, t, 0.5f);
}
__device__ __forceinline__ float fast_exp8(float x) {   // exp(x/8)
    float e;
    asm("ex2.approx.f32 %0, %1;" : "=f"(e) : "f"(x * 0.18033688011112042f));
    return e;
}

__global__ __launch_bounds__(NT, 8)
void attn_kernel(const float* __restrict__ q,
                 const float* __restrict__ k,
                 const int*   __restrict__ kes_length,
                 const float* __restrict__ fs,
                 const float* __restrict__ bias,
                 const float* __restrict__ Wq,
                 const float* __restrict__ Wk,
                 const float* __restrict__ Wv,
                 float*       __restrict__ out) {
    __shared__ float kstage[8 * 2 * BFLOATS];  // per-warp double buffers (20 KB)
    __shared__ float spart[16 * DD];           // 16 half-warp partials (4 KB)
    __shared__ float squ[DD];
    __shared__ float stmp[DD];
    __shared__ float su[DD];
    __shared__ float swr[16];

    const int b    = blockIdx.x;
    const int tid  = threadIdx.x;
    const int lane = tid & 31;
    const int warp = tid >> 5;           // 0..7
    const int half = lane >> 4;          // 0/1 within warp
    const int hw   = tid >> 4;           // half-warp id 0..15
    const int l16  = tid & 15;

    const float* kb = k + (size_t)b * MAXLEN * DD;
    const int rbase = warp * RPW;

    // per-warp staging buffers
    float* buf0 = kstage + (warp * 2 + 0) * BFLOATS;
    float* buf1 = kstage + (warp * 2 + 1) * BFLOATS;
    const uint32_t sb0 = (uint32_t)__cvta_generic_to_shared(buf0);
    const uint32_t sb1 = (uint32_t)__cvta_generic_to_shared(buf1);

    // ---- issue this warp's batches 0 and 1 immediately ----
    {
        const char* g0 = (const char*)(kb + rbase * DD);
#pragma unroll
        for (int u = lane; u < BUNITS; u += 32)
            cp_async16(sb0 + u * 16, g0 + u * 16);
        cp_commit();
        const char* g1 = (const char*)(kb + (rbase + BT) * DD);
#pragma unroll
        for (int u = lane; u < BUNITS; u += 32)
            cp_async16(sb1 + u * 16, g1 + u * 16);
        cp_commit();
    }

    // ---- qbar[d] = sum_f fs[f] * q[b,f,d]  (float4, 16-way f split) ----
    {
        const float4* qb4 = (const float4*)(q + (size_t)b * FF * DD);
        float4 a = make_float4(0.f, 0.f, 0.f, 0.f);
#pragma unroll
        for (int fi = 0; fi < 4; ++fi) {
            int f = hw + 16 * fi;
            float s = fs[f];
            float4 v = qb4[f * 16 + l16];
            a.x += s * v.x; a.y += s * v.y; a.z += s * v.z; a.w += s * v.w;
        }
        ((float4*)spart)[hw * 16 + l16] = a;
    }
    __syncthreads();
    if (tid < DD) {
        float s = 0.f;
#pragma unroll
        for (int i = 0; i < 16; ++i) s += spart[i * DD + tid];
        squ[tid] = s;
    }
    __syncthreads();

    // ---- tmp[e] = sum_c qbar[c] * Wq[c,e] ----
    {
        float4 a = make_float4(0.f, 0.f, 0.f, 0.f);
#pragma unroll
        for (int ci = 0; ci < 4; ++ci) {
            int c = hw * 4 + ci;
            float s = squ[c];
            float4 v = ((const float4*)Wq)[c * 16 + l16];
            a.x += s * v.x; a.y += s * v.y; a.z += s * v.z; a.w += s * v.w;
        }
        ((float4*)spart)[hw * 16 + l16] = a;
    }
    __syncthreads();
    if (tid < DD) {
        float s = 0.f;
#pragma unroll
        for (int i = 0; i < 16; ++i) s += spart[i * DD + tid];
        stmp[tid] = s;
    }
    __syncthreads();

    // ---- u[row] = sum_e tmp[e] * Wk[row,e]  (half-warp per row) ----
    {
        float4 tv = ((const float4*)stmp)[l16];
#pragma unroll
        for (int r = 0; r < 4; ++r) {
            int row = hw + 16 * r;
            float4 wv = ((const float4*)(Wk + row * DD))[l16];
            float p = wv.x * tv.x + wv.y * tv.y + wv.z * tv.z + wv.w * tv.w;
#pragma unroll
            for (int o = 8; o; o >>= 1)
                p += __shfl_xor_sync(0xffffffffu, p, o);
            if (l16 == 0) su[row] = p;
        }
    }
    __syncthreads();   // <- LAST barrier before the end-of-stream reduction

    // ---- per-warp independent streaming: no CTA barriers below ----
    const int   len   = kes_length[b];
    const float biasD = bias[0] * (float)DD;
    const float mfill = (len == 0) ? 1.f : 0.f;
    const float4 uv   = ((const float4*)su)[l16];

    float4 wa   = make_float4(0.f, 0.f, 0.f, 0.f);
    float  esum = 0.f;

#pragma unroll
    for (int bt = 0; bt < NBATCH; ++bt) {
        if (bt < NBATCH - 1) cp_wait<1>(); else cp_wait<0>();

        const float4* bf = (const float4*)((bt & 1) ? buf1 : buf0);
#pragma unroll
        for (int p = 0; p < 3; ++p) {
            int  r     = p * 2 + half;        // 0..5 ; r==5 invalid
            bool valid = (r < BT);
            float4 kv  = bf[(valid ? r : 0) * 16 + l16];
            float pd = kv.x * uv.x + kv.y * uv.y + kv.z * uv.z + kv.w * uv.w;
#pragma unroll
            for (int o = 8; o; o >>= 1)
                pd += __shfl_xor_sync(0xffffffffu, pd, o);  // within half-warp
            int   t = rbase + bt * BT + r;
            float e = 0.f;
            if (valid)
                e = (t < len) ? fast_exp8(fast_sigmoid(pd + biasD)) : mfill;
            wa.x += e * kv.x; wa.y += e * kv.y;
            wa.z += e * kv.z; wa.w += e * kv.w;
            esum += e;
        }

        if (bt + 2 < NBATCH) {   // refill the buffer we just drained
            const char* gn = (const char*)(kb + (rbase + (bt + 2) * BT) * DD);
            uint32_t sbn = (bt & 1) ? sb1 : sb0;
#pragma unroll
            for (int u = lane; u < BUNITS; u += 32)
                cp_async16(sbn + u * 16, gn + u * 16);
            cp_commit();
        }
    }

    // ---- join + cross-half-warp reduce ----
    __syncthreads();            // protect spart reuse
    ((float4*)spart)[hw * 16 + l16] = wa;
    if (l16 == 0) swr[hw] = esum;
    __syncthreads();

    if (tid < DD) {
        float s = 0.f;
#pragma unroll
        for (int i = 0; i < 16; ++i) s += spart[i * DD + tid];
        su[tid] = s;
    }
    __syncthreads();

    // ---- out[b,e] = inv * sum_c w[c] * Wv[c,e] ----
    {
        float4 a = make_float4(0.f, 0.f, 0.f, 0.f);
#pragma unroll
        for (int ci = 0; ci < 4; ++ci) {
            int c = hw * 4 + ci;
            float s = su[c];
            float4 v = ((const float4*)Wv)[c * 16 + l16];
            a.x += s * v.x; a.y += s * v.y; a.z += s * v.z; a.w += s * v.w;
        }
        ((float4*)spart)[hw * 16 + l16] = a;
    }
    __syncthreads();
    if (tid < DD) {
        float tot = 0.f;
#pragma unroll
        for (int i = 0; i < 16; ++i) tot += swr[i];
        float s = 0.f;
#pragma unroll
        for (int i = 0; i < 16; ++i) s += spart[i * DD + tid];
        out[(size_t)b * DD + tid] = s * (1.f / tot);
    }
}

extern "C" void kernel_launch(void* const* d_in, const int* in_sizes, int n_in,
                              void* d_out, int out_size) {
    const float* q    = (const float*)d_in[0];
    const float* k    = (const float*)d_in[1];
    // d_in[2] = v : unused by the reference computation
    const int*   kes  = (const int*)  d_in[3];
    const float* fs   = (const float*)d_in[4];
    const float* bias = (const float*)d_in[5];
    const float* Wq   = (const float*)d_in[6];
    const float* Wk   = (const float*)d_in[7];
    const float* Wv   = (const float*)d_in[8];
    float*       out  = (float*)d_out;

    cudaFuncSetAttribute(attn_kernel, cudaFuncAttributePreferredSharedMemoryCarveout, 100);
    attn_kernel<<<BB, NT>>>(q, k, kes, fs, bias, Wq, Wk, Wv, out);
}